// round 10
// baseline (speedup 1.0000x reference)
#include <cuda_runtime.h>
#include <cuda_fp16.h>
#include <cstdint>
#include <cstddef>

#define NN   25000
#define EE   50000
#define EE3  40000
#define DIM  64

// Wedge stored as e4m3 scaled by 32 (decoded value = stored/32)
#define WSCALE     32.0f
#define WSCALE_INV 0.03125f

// ---------------- scratch (device globals; no allocation at launch time) ----
__device__ float   g_h[NN * DIM];                      // node features / GRU state
__device__ float   g_agg[NN * DIM];                    // scatter-sum accumulator
__device__ __half  g_hr_h[EE * 128];                   // edge hidden (fp16)
__device__ __half  g_W2T[4096 * 128];                  // W_e2 transposed fp16 [col][k]
__device__ uint8_t g_Wedge8[(size_t)EE * DIM * DIM];   // 205 MB per-edge weights (e4m3*32)
__device__ float   g_cnt[NN];
__device__ float   g_invcnt[NN];

// ---------------- helpers -----------------------------------------------------
__device__ __forceinline__ uint32_t smem_to_u32(const void* p) {
    uint32_t a;
    asm("{ .reg .u64 t; cvta.to.shared.u64 t, %1; cvt.u32.u64 %0, t; }"
        : "=r"(a) : "l"(p));
    return a;
}
__device__ __forceinline__ void ldsm4(uint32_t* r, uint32_t addr) {
    asm volatile("ldmatrix.sync.aligned.m8n8.x4.shared.b16 {%0,%1,%2,%3}, [%4];"
                 : "=r"(r[0]), "=r"(r[1]), "=r"(r[2]), "=r"(r[3]) : "r"(addr));
}
// fp32-accumulate HMMA (full rate on sm_103; fp16-acc measured SLOWER)
__device__ __forceinline__ void mma16816(float* d, const uint32_t* a,
                                         const uint32_t* b) {
    asm volatile(
        "mma.sync.aligned.m16n8k16.row.col.f32.f16.f16.f32 "
        "{%0,%1,%2,%3}, {%4,%5,%6,%7}, {%8,%9}, {%0,%1,%2,%3};"
        : "+f"(d[0]), "+f"(d[1]), "+f"(d[2]), "+f"(d[3])
        : "r"(a[0]), "r"(a[1]), "r"(a[2]), "r"(a[3]), "r"(b[0]), "r"(b[1]));
}
__device__ __forceinline__ uint16_t f32x2_to_e4m3(float lo, float hi) {
    uint16_t r;
    asm("cvt.rn.satfinite.e4m3x2.f32 %0, %1, %2;" : "=h"(r) : "f"(hi), "f"(lo));
    return r;
}
__device__ __forceinline__ uint32_t e4m3x2_to_f16x2(uint16_t v) {
    uint32_t r;
    asm("cvt.rn.f16x2.e4m3x2 %0, %1;" : "=r"(r) : "h"(v));
    return r;
}
__device__ __forceinline__ unsigned long long fma2(unsigned long long a,
                                                   unsigned long long b,
                                                   unsigned long long c) {
    unsigned long long d;
    asm("fma.rn.f32x2 %0, %1, %2, %3;" : "=l"(d) : "l"(a), "l"(b), "l"(c));
    return d;
}
__device__ __forceinline__ float2 unpack2(unsigned long long v) {
    float2 r;
    asm("mov.b64 {%0, %1}, %2;" : "=f"(r.x), "=f"(r.y) : "l"(v));
    return r;
}

// ---------------- fused prep: node MLP + zero agg + zero cnt ------------------
__global__ void prep_kernel(const float* __restrict__ x,
                            const float* __restrict__ Wn,
                            const float* __restrict__ bn, int N) {
    int i = blockIdx.x * 256 + threadIdx.x;
    if (i < N) g_cnt[i] = 0.f;
    if (i >= N * DIM) return;
    g_agg[i] = 0.f;
    int n = i >> 6, f = i & 63;
    float acc = bn[f];
#pragma unroll
    for (int k = 0; k < 8; k++) acc += x[n * 8 + k] * Wn[k * DIM + f];
    g_h[i] = fmaxf(acc, 0.f);
}

__global__ void count_kernel(const int* __restrict__ dst, int E) {
    int e = blockIdx.x * 256 + threadIdx.x;
    if (e < E) atomicAdd(&g_cnt[dst[e]], 1.f);
}
__global__ void invcnt_kernel(int N) {
    int i = blockIdx.x * 256 + threadIdx.x;
    if (i < N) g_invcnt[i] = 1.f / fmaxf(g_cnt[i], 1.f);
}

// ---------------- fused edge MLP + W_e2 transpose ------------------------------
__global__ void __launch_bounds__(128) edge_w2t_kernel(
    const float* __restrict__ ea_in, const float* __restrict__ W_ea,
    const float* __restrict__ b_ea, const float* __restrict__ W_e1,
    const float* __restrict__ b_e1, const float* __restrict__ W2, int E) {
    int tid = threadIdx.x;
    if ((int)blockIdx.x >= E) {
        int i = ((int)blockIdx.x - E) * 128 + tid;
        int n = i & 4095, k = i >> 12;
        g_W2T[(size_t)n * 128 + k] = __float2half(W2[(size_t)k * 4096 + n]);
        return;
    }
    __shared__ float row[19];
    __shared__ float eah[12];
    int e = blockIdx.x;
    if (tid < 19) row[tid] = ea_in[(size_t)e * 19 + tid];
    __syncthreads();
    if (tid < 12) {
        float a = b_ea[tid];
#pragma unroll
        for (int i = 0; i < 19; i++) a += row[i] * W_ea[i * 12 + tid];
        eah[tid] = fmaxf(a, 0.f);
    }
    __syncthreads();
    float a = b_e1[tid];
#pragma unroll
    for (int k = 0; k < 12; k++) a += eah[k] * W_e1[k * 128 + tid];
    g_hr_h[(size_t)e * 128 + tid] = __float2half(fmaxf(a, 0.f));
}

// ============ HMMA Wedge GEMM (R6-exact: fp32 acc, 8 warps, 32x64 tiles) ======
#define WSTRIDE 136
#define AS_OFF  0
#define BS_OFF  (128 * WSTRIDE * 2)
#define BIAS_OFF (2 * 128 * WSTRIDE * 2)
#define WM_SMEM_SIZE (BIAS_OFF + 128 * 4)
#define CBSTR 144   // byte stride of fp8 staging rows (16-aligned)

__global__ void __launch_bounds__(256) wedge_mma_kernel(
    const float* __restrict__ b2, int E) {
    extern __shared__ char smem[];
    __half* As = (__half*)(smem + AS_OFF);
    __half* Bs = (__half*)(smem + BS_OFF);
    float* sbias = (float*)(smem + BIAS_OFF);
    uint32_t sbase = smem_to_u32(smem);
    int tid = threadIdx.x;
    int ebase = blockIdx.x * 128;
    int colbase = blockIdx.y * 128;

    if (tid < 128) sbias[tid] = b2[colbase + tid];

#pragma unroll
    for (int it = 0; it < 8; it++) {
        int idx = it * 256 + tid;
        int r = idx >> 4, c = idx & 15;
        uint4 v = make_uint4(0, 0, 0, 0);
        if (ebase + r < E)
            v = *(const uint4*)(g_hr_h + ((size_t)(ebase + r) << 7) + c * 8);
        *(uint4*)(As + r * WSTRIDE + c * 8) = v;
    }
#pragma unroll
    for (int it = 0; it < 8; it++) {
        int idx = it * 256 + tid;
        int r = idx >> 4, c = idx & 15;
        uint4 v = *(const uint4*)(g_W2T + ((size_t)(colbase + r) << 7) + c * 8);
        *(uint4*)(Bs + r * WSTRIDE + c * 8) = v;
    }
    __syncthreads();

    int w = tid >> 5, lane = tid & 31;
    int wm = (w & 3) * 32;
    int wn = (w >> 2) * 64;

    float acc[2][8][4];
#pragma unroll
    for (int i = 0; i < 2; i++)
#pragma unroll
        for (int j = 0; j < 8; j++)
#pragma unroll
            for (int q = 0; q < 4; q++) acc[i][j][q] = 0.f;

    uint32_t a_addr[2];
#pragma unroll
    for (int i = 0; i < 2; i++)
        a_addr[i] = sbase + AS_OFF +
                    (uint32_t)((wm + i * 16 + (lane & 15)) * WSTRIDE +
                               (lane >> 4) * 8) * 2;
    uint32_t b_addr[4];
#pragma unroll
    for (int jj = 0; jj < 4; jj++)
        b_addr[jj] = sbase + BS_OFF +
                     (uint32_t)((wn + jj * 16 + ((lane >> 4) & 1) * 8 + (lane & 7)) *
                                    WSTRIDE +
                                ((lane >> 3) & 1) * 8) * 2;

#pragma unroll
    for (int s = 0; s < 8; s++) {
        uint32_t a[2][4], b[4][4];
#pragma unroll
        for (int i = 0; i < 2; i++) ldsm4(a[i], a_addr[i] + s * 32);
#pragma unroll
        for (int jj = 0; jj < 4; jj++) ldsm4(b[jj], b_addr[jj] + s * 32);
#pragma unroll
        for (int i = 0; i < 2; i++)
#pragma unroll
            for (int jj = 0; jj < 4; jj++) {
                mma16816(acc[i][2 * jj], a[i], &b[jj][0]);
                mma16816(acc[i][2 * jj + 1], a[i], &b[jj][2]);
            }
    }
    __syncthreads();   // reuse smem as fp8 staging

    uint8_t* Cs = (uint8_t*)smem;
    int g = lane >> 2, tg = lane & 3;
#pragma unroll
    for (int i = 0; i < 2; i++) {
#pragma unroll
        for (int j = 0; j < 8; j++) {
            int col = wn + j * 8 + tg * 2;
            float b0 = sbias[col], b1 = sbias[col + 1];
            int r0 = wm + i * 16 + g;
            uint16_t p0 = f32x2_to_e4m3((acc[i][j][0] + b0) * WSCALE,
                                        (acc[i][j][1] + b1) * WSCALE);
            uint16_t p1 = f32x2_to_e4m3((acc[i][j][2] + b0) * WSCALE,
                                        (acc[i][j][3] + b1) * WSCALE);
            *(uint16_t*)(Cs + r0 * CBSTR + col) = p0;
            *(uint16_t*)(Cs + (r0 + 8) * CBSTR + col) = p1;
        }
    }
    __syncthreads();

#pragma unroll
    for (int it = 0; it < 4; it++) {
        int idx = it * 256 + tid;
        int r = idx >> 3, c = idx & 7;
        if (ebase + r < E) {
            uint4 v = *(const uint4*)(Cs + r * CBSTR + c * 16);
            *(uint4*)(g_Wedge8 + (size_t)(ebase + r) * 4096 + colbase + c * 16) = v;
        }
    }
}

// msg[e] = h[src[e]] @ Wedge8[e]; HFMA2 accumulation, scatter via atomics.
// 64 edges/block, 4 threads/edge x 16 cols; unroll 8 for MLP.
__global__ void __launch_bounds__(256) msg_scatter_kernel(
    const int* __restrict__ src, const int* __restrict__ dst, int E) {
    __shared__ uint32_t souts[64][68];
    __shared__ int sdst[64];
    int ty = threadIdx.x >> 2;
    int tx = threadIdx.x & 3;
    int e = blockIdx.x * 64 + ty;
    if (e < E) {
        int s = src[e];
#pragma unroll
        for (int q = 0; q < 4; q++) {
            float4 v = *(const float4*)&g_h[(size_t)s * 64 + tx * 16 + q * 4];
            __half hx = __float2half(v.x), hy = __float2half(v.y);
            __half hz = __float2half(v.z), hw = __float2half(v.w);
            __half2 d0 = __halves2half2(hx, hx);
            __half2 d1 = __halves2half2(hy, hy);
            __half2 d2 = __halves2half2(hz, hz);
            __half2 d3 = __halves2half2(hw, hw);
            souts[ty][tx * 16 + q * 4 + 0] = *(uint32_t*)&d0;
            souts[ty][tx * 16 + q * 4 + 1] = *(uint32_t*)&d1;
            souts[ty][tx * 16 + q * 4 + 2] = *(uint32_t*)&d2;
            souts[ty][tx * 16 + q * 4 + 3] = *(uint32_t*)&d3;
        }
        if (tx == 0) sdst[ty] = dst[e];
    }
    __syncthreads();
    if (e >= E) return;
    __half2 hacc[8];
#pragma unroll
    for (int j = 0; j < 8; j++) hacc[j] = __halves2half2(__ushort_as_half(0),
                                                         __ushort_as_half(0));
    const uint8_t* Wrow = g_Wedge8 + (size_t)e * 4096 + tx * 16;
#pragma unroll 8
    for (int d = 0; d < 64; d++) {
        uint32_t a2 = souts[ty][d];
        __half2 ah = *(__half2*)&a2;
        uint4 raw = *(const uint4*)(Wrow + d * 64);
        uint32_t ws[4] = {raw.x, raw.y, raw.z, raw.w};
#pragma unroll
        for (int q = 0; q < 4; q++) {
            uint32_t lo = e4m3x2_to_f16x2((uint16_t)ws[q]);
            uint32_t hi = e4m3x2_to_f16x2((uint16_t)(ws[q] >> 16));
            hacc[2 * q]     = __hfma2(ah, *(__half2*)&lo, hacc[2 * q]);
            hacc[2 * q + 1] = __hfma2(ah, *(__half2*)&hi, hacc[2 * q + 1]);
        }
    }
    int dn = sdst[ty];
    float* ap = g_agg + (size_t)dn * 64 + tx * 16;
#pragma unroll
    for (int j = 0; j < 8; j++) {
        float2 f = __half22float2(hacc[j]);
        atomicAdd(ap + 2 * j, f.x * WSCALE_INV);
        atomicAdd(ap + 2 * j + 1, f.y * WSCALE_INV);
    }
}

// GRU update: 64 nodes/block, 1024 threads (4x less weight-staging traffic);
// f32x2 over k-pairs; clears g_agg after reading.
#define GRU_NODES 64
#define GRU_THREADS 1024
#define GRU_SMEM_FLOATS (2 * 192 * 66 + 2 * GRU_NODES * 64)
__global__ void __launch_bounds__(GRU_THREADS) gru_kernel(
    const float* __restrict__ conv_bias,
    const float* __restrict__ W_ih, const float* __restrict__ b_ih,
    const float* __restrict__ W_hh, const float* __restrict__ b_hh, int N) {
    extern __shared__ float sm[];
    float* wih = sm;                     // [192][66] padded
    float* whh = sm + 192 * 66;
    float* ms  = whh + 192 * 66;         // [64][64]
    float* hs  = ms + GRU_NODES * 64;
    int tid = threadIdx.x;
    for (int i = tid; i < 192 * 16; i += GRU_THREADS) {
        int r = i >> 4, c4 = i & 15;
        float4 a = *(const float4*)&W_ih[r * 64 + c4 * 4];
        float4 b = *(const float4*)&W_hh[r * 64 + c4 * 4];
        *(float2*)&wih[r * 66 + c4 * 4] = make_float2(a.x, a.y);
        *(float2*)&wih[r * 66 + c4 * 4 + 2] = make_float2(a.z, a.w);
        *(float2*)&whh[r * 66 + c4 * 4] = make_float2(b.x, b.y);
        *(float2*)&whh[r * 66 + c4 * 4 + 2] = make_float2(b.z, b.w);
    }
    int nb = blockIdx.x * GRU_NODES;
    for (int i = tid; i < GRU_NODES * 64; i += GRU_THREADS) {
        int nl = i >> 6, f = i & 63;
        int n = nb + nl;
        if (n < N) {
            ms[nl * 64 + f] =
                fmaxf(g_agg[(size_t)n * 64 + f] * g_invcnt[n] + conv_bias[f], 0.f);
            g_agg[(size_t)n * 64 + f] = 0.f;
            hs[nl * 64 + f] = g_h[(size_t)n * 64 + f];
        }
    }
    __syncthreads();
    int lane = tid & 63;   // feature f
    int grp = tid >> 6;    // 0..15 -> nodes grp*4 .. grp*4+3
    unsigned long long aR[4], aZ[4], aN[4], bR[4], bZ[4], bN[4];
#pragma unroll
    for (int j = 0; j < 4; j++) {
        aR[j] = aZ[j] = aN[j] = 0ull;
        bR[j] = bZ[j] = bN[j] = 0ull;
    }
    const float* msg = ms + grp * 4 * 64;
    const float* hsg = hs + grp * 4 * 64;
#pragma unroll 4
    for (int k = 0; k < 64; k += 2) {
        unsigned long long w0 = *(const unsigned long long*)&wih[lane * 66 + k];
        unsigned long long w1 = *(const unsigned long long*)&wih[(64 + lane) * 66 + k];
        unsigned long long w2 = *(const unsigned long long*)&wih[(128 + lane) * 66 + k];
        unsigned long long v0 = *(const unsigned long long*)&whh[lane * 66 + k];
        unsigned long long v1 = *(const unsigned long long*)&whh[(64 + lane) * 66 + k];
        unsigned long long v2 = *(const unsigned long long*)&whh[(128 + lane) * 66 + k];
#pragma unroll
        for (int j = 0; j < 4; j++) {
            unsigned long long mk = *(const unsigned long long*)&msg[j * 64 + k];
            unsigned long long hk = *(const unsigned long long*)&hsg[j * 64 + k];
            aR[j] = fma2(mk, w0, aR[j]);
            aZ[j] = fma2(mk, w1, aZ[j]);
            aN[j] = fma2(mk, w2, aN[j]);
            bR[j] = fma2(hk, v0, bR[j]);
            bZ[j] = fma2(hk, v1, bZ[j]);
            bN[j] = fma2(hk, v2, bN[j]);
        }
    }
    float bir = b_ih[lane], biz = b_ih[64 + lane], bin = b_ih[128 + lane];
    float bhr = b_hh[lane], bhz = b_hh[64 + lane], bhn = b_hh[128 + lane];
#pragma unroll
    for (int j = 0; j < 4; j++) {
        int n = nb + grp * 4 + j;
        if (n >= N) continue;
        float2 pr = unpack2(aR[j]);
        float2 pz = unpack2(aZ[j]);
        float2 pn = unpack2(aN[j]);
        float2 qr = unpack2(bR[j]);
        float2 qz = unpack2(bZ[j]);
        float2 qn = unpack2(bN[j]);
        float ir = pr.x + pr.y + bir, iz = pz.x + pz.y + biz, inn = pn.x + pn.y + bin;
        float hrr = qr.x + qr.y + bhr, hz = qz.x + qz.y + bhz, hn = qn.x + qn.y + bhn;
        float r = 1.f / (1.f + __expf(-(ir + hrr)));
        float z = 1.f / (1.f + __expf(-(iz + hz)));
        float ng = tanhf(inn + r * hn);
        g_h[(size_t)n * 64 + lane] = (1.f - z) * ng + z * hsg[j * 64 + lane];
    }
}

// final MLP: warp-per-edge, weights staged once, no block syncs in edge loop.
#define FIN_EDGES 64
__global__ void __launch_bounds__(128) final_mlp_kernel(
    const float* __restrict__ ea3, const int* __restrict__ idx_a,
    const int* __restrict__ idx_b, const float* __restrict__ W_l1,
    const float* __restrict__ b_l1, const float* __restrict__ W_l2,
    const float* __restrict__ b_l2, float* __restrict__ out, int E3) {
    __shared__ float wl1[72 * 128];
    __shared__ float swl2[128];
    __shared__ float sbl1[128];
    __shared__ float feat[4][72];
    int tid = threadIdx.x;
    for (int i = tid; i < 72 * 128; i += 128) wl1[i] = W_l1[i];
    swl2[tid] = W_l2[tid];
    sbl1[tid] = b_l1[tid];
    __syncthreads();
    int w = tid >> 5, lane = tid & 31;
    float bl2v = b_l2[0];
    int base = blockIdx.x * FIN_EDGES;
    for (int t = w; t < FIN_EDGES; t += 4) {
        int e = base + t;
        if (e >= E3) break;
        int a = idx_a[e], b = idx_b[e];
        feat[w][lane] =
            0.5f * (g_h[(size_t)a * 64 + lane] + g_h[(size_t)b * 64 + lane]);
        feat[w][32 + lane] = 0.5f * (g_h[(size_t)a * 64 + 32 + lane] +
                                     g_h[(size_t)b * 64 + 32 + lane]);
        if (lane < 8) feat[w][64 + lane] = ea3[(size_t)e * 8 + lane];
        __syncwarp();
        float a0 = sbl1[lane], a1 = sbl1[lane + 32],
              a2 = sbl1[lane + 64], a3 = sbl1[lane + 96];
#pragma unroll 8
        for (int i = 0; i < 72; i++) {
            float f = feat[w][i];
            a0 += f * wl1[i * 128 + lane];
            a1 += f * wl1[i * 128 + lane + 32];
            a2 += f * wl1[i * 128 + lane + 64];
            a3 += f * wl1[i * 128 + lane + 96];
        }
        float s = fmaxf(a0, 0.f) * swl2[lane] + fmaxf(a1, 0.f) * swl2[lane + 32] +
                  fmaxf(a2, 0.f) * swl2[lane + 64] + fmaxf(a3, 0.f) * swl2[lane + 96];
#pragma unroll
        for (int o = 16; o > 0; o >>= 1) s += __shfl_down_sync(0xffffffffu, s, o);
        if (lane == 0) out[e] = s + bl2v;
        __syncwarp();
    }
}

// ---------------- launch ------------------------------------------------------
extern "C" void kernel_launch(void* const* d_in, const int* in_sizes, int n_in,
                              void* d_out, int out_size) {
    const float* x          = (const float*)d_in[0];
    const float* edge_attr  = (const float*)d_in[1];
    const float* edge_attr3 = (const float*)d_in[2];
    const int*   edge_index  = (const int*)d_in[3];
    const int*   edge_index3 = (const int*)d_in[4];
    const float* W_node = (const float*)d_in[5];
    const float* b_node = (const float*)d_in[6];
    const float* W_ea   = (const float*)d_in[7];
    const float* b_ea   = (const float*)d_in[8];
    const float* W_e1   = (const float*)d_in[9];
    const float* b_e1   = (const float*)d_in[10];
    const float* W_e2   = (const float*)d_in[11];
    const float* b_e2   = (const float*)d_in[12];
    const float* conv_bias = (const float*)d_in[13];
    const float* W_ih = (const float*)d_in[14];
    const float* b_ih = (const float*)d_in[15];
    const float* W_hh = (const float*)d_in[16];
    const float* b_hh = (const float*)d_in[17];
    const float* W_l1 = (const float*)d_in[18];
    const float* b_l1 = (const float*)d_in[19];
    const float* W_l2 = (const float*)d_in[20];
    const float* b_l2 = (const float*)d_in[21];

    int N  = in_sizes[0] / 8;
    int E  = in_sizes[1] / 19;
    int E3 = in_sizes[2] / 8;
    const int* src  = edge_index;
    const int* dst  = edge_index + E;
    const int* e3a  = edge_index3;
    const int* e3b  = edge_index3 + E3;
    float* out = (float*)d_out;

    cudaFuncSetAttribute(gru_kernel, cudaFuncAttributeMaxDynamicSharedMemorySize,
                         GRU_SMEM_FLOATS * (int)sizeof(float));
    cudaFuncSetAttribute(wedge_mma_kernel,
                         cudaFuncAttributeMaxDynamicSharedMemorySize, WM_SMEM_SIZE);

    // (1) node MLP + zero agg/cnt
    prep_kernel<<<(N * DIM + 255) / 256, 256>>>(x, W_node, b_node, N);
    // (2) edge MLP + W_e2 transpose (fused)
    edge_w2t_kernel<<<E + 4096, 128>>>(edge_attr, W_ea, b_ea, W_e1, b_e1, W_e2, E);
    // (3) big GEMM on tensor cores -> Wedge (e4m3*32)
    {
        dim3 grid((E + 127) / 128, 32);
        wedge_mma_kernel<<<grid, 256, WM_SMEM_SIZE>>>(b_e2, E);
    }
    // (4) msg iter 0
    msg_scatter_kernel<<<(E + 63) / 64, 256>>>(src, dst, E);
    // (5,6) degree counts
    count_kernel<<<(E + 255) / 256, 256>>>(dst, E);
    invcnt_kernel<<<(N + 255) / 256, 256>>>(N);
    // (7) gru 0 (clears agg)
    gru_kernel<<<(N + GRU_NODES - 1) / GRU_NODES, GRU_THREADS,
                 GRU_SMEM_FLOATS * (int)sizeof(float)>>>(
        conv_bias, W_ih, b_ih, W_hh, b_hh, N);
    for (int it = 1; it < 3; it++) {
        msg_scatter_kernel<<<(E + 63) / 64, 256>>>(src, dst, E);
        gru_kernel<<<(N + GRU_NODES - 1) / GRU_NODES, GRU_THREADS,
                     GRU_SMEM_FLOATS * (int)sizeof(float)>>>(
            conv_bias, W_ih, b_ih, W_hh, b_hh, N);
    }
    // final pair MLP
    final_mlp_kernel<<<(E3 + FIN_EDGES - 1) / FIN_EDGES, 128>>>(
        edge_attr3, e3a, e3b, W_l1, b_l1, W_l2, b_l2, out, E3);
}

// round 11
// speedup vs baseline: 1.5666x; 1.5666x over previous
#include <cuda_runtime.h>
#include <cuda_fp16.h>
#include <cstdint>
#include <cstddef>

#define NN   25000
#define EE   50000
#define EE3  40000
#define DIM  64

// Wedge stored as e4m3 scaled by 32 (decoded value = stored/32)
#define WSCALE     32.0f
#define WSCALE_INV 0.03125f

// ---------------- scratch (device globals; no allocation at launch time) ----
__device__ float   g_h[NN * DIM];                      // node features / GRU state
__device__ float   g_agg[NN * DIM];                    // scatter-sum accumulator
__device__ __half  g_hr_h[EE * 128];                   // edge hidden (fp16)
__device__ __half  g_W2T[4096 * 128];                  // W_e2 transposed fp16 [col][k]
__device__ uint8_t g_Wedge8[(size_t)EE * DIM * DIM];   // 205 MB per-edge weights (e4m3*32)
__device__ float   g_cnt[NN];
__device__ float   g_invcnt[NN];
__device__ __half  g_WcatT[256 * 128];                 // GRU gate weights [gate][k]
__device__ __half  g_mh[(size_t)NN * 128];             // [m|h] fp16 per node
__device__ float   g_gates[(size_t)NN * 256];          // GEMM gate outputs

// ---------------- helpers -----------------------------------------------------
__device__ __forceinline__ uint32_t smem_to_u32(const void* p) {
    uint32_t a;
    asm("{ .reg .u64 t; cvta.to.shared.u64 t, %1; cvt.u32.u64 %0, t; }"
        : "=r"(a) : "l"(p));
    return a;
}
__device__ __forceinline__ void ldsm4(uint32_t* r, uint32_t addr) {
    asm volatile("ldmatrix.sync.aligned.m8n8.x4.shared.b16 {%0,%1,%2,%3}, [%4];"
                 : "=r"(r[0]), "=r"(r[1]), "=r"(r[2]), "=r"(r[3]) : "r"(addr));
}
// fp32-accumulate HMMA (full rate on sm_103; fp16-acc measured SLOWER)
__device__ __forceinline__ void mma16816(float* d, const uint32_t* a,
                                         const uint32_t* b) {
    asm volatile(
        "mma.sync.aligned.m16n8k16.row.col.f32.f16.f16.f32 "
        "{%0,%1,%2,%3}, {%4,%5,%6,%7}, {%8,%9}, {%0,%1,%2,%3};"
        : "+f"(d[0]), "+f"(d[1]), "+f"(d[2]), "+f"(d[3])
        : "r"(a[0]), "r"(a[1]), "r"(a[2]), "r"(a[3]), "r"(b[0]), "r"(b[1]));
}
__device__ __forceinline__ uint16_t f32x2_to_e4m3(float lo, float hi) {
    uint16_t r;
    asm("cvt.rn.satfinite.e4m3x2.f32 %0, %1, %2;" : "=h"(r) : "f"(hi), "f"(lo));
    return r;
}
__device__ __forceinline__ uint32_t e4m3x2_to_f16x2(uint16_t v) {
    uint32_t r;
    asm("cvt.rn.f16x2.e4m3x2 %0, %1;" : "=r"(r) : "h"(v));
    return r;
}

// ---------------- fused prep: node MLP + zero agg + zero cnt ------------------
__global__ void prep_kernel(const float* __restrict__ x,
                            const float* __restrict__ Wn,
                            const float* __restrict__ bn, int N) {
    int i = blockIdx.x * 256 + threadIdx.x;
    if (i < N) g_cnt[i] = 0.f;
    if (i >= N * DIM) return;
    g_agg[i] = 0.f;
    int n = i >> 6, f = i & 63;
    float acc = bn[f];
#pragma unroll
    for (int k = 0; k < 8; k++) acc += x[n * 8 + k] * Wn[k * DIM + f];
    g_h[i] = fmaxf(acc, 0.f);
}

__global__ void count_kernel(const int* __restrict__ dst, int E) {
    int e = blockIdx.x * 256 + threadIdx.x;
    if (e < E) atomicAdd(&g_cnt[dst[e]], 1.f);
}
__global__ void invcnt_kernel(int N) {
    int i = blockIdx.x * 256 + threadIdx.x;
    if (i < N) g_invcnt[i] = 1.f / fmaxf(g_cnt[i], 1.f);
}

// build WcatT[256][128]: rows 0-63 [Wih_r|Whh_r], 64-127 [Wih_z|Whh_z],
// 128-191 [Wih_n|0], 192-255 [0|Whh_n]
__global__ void wcat_kernel(const float* __restrict__ W_ih,
                            const float* __restrict__ W_hh) {
    int i = blockIdx.x * 256 + threadIdx.x;
    if (i >= 256 * 128) return;
    int g = i >> 7, k = i & 127;
    float v;
    if (g < 128)      v = (k < 64) ? W_ih[g * 64 + k] : W_hh[g * 64 + (k - 64)];
    else if (g < 192) v = (k < 64) ? W_ih[g * 64 + k] : 0.f;
    else              v = (k >= 64) ? W_hh[(g - 64) * 64 + (k - 64)] : 0.f;
    g_WcatT[g * 128 + k] = __float2half(v);
}

// ---------------- fused edge MLP + W_e2 transpose ------------------------------
__global__ void __launch_bounds__(128) edge_w2t_kernel(
    const float* __restrict__ ea_in, const float* __restrict__ W_ea,
    const float* __restrict__ b_ea, const float* __restrict__ W_e1,
    const float* __restrict__ b_e1, const float* __restrict__ W2, int E) {
    int tid = threadIdx.x;
    if ((int)blockIdx.x >= E) {
        int i = ((int)blockIdx.x - E) * 128 + tid;
        int n = i & 4095, k = i >> 12;
        g_W2T[(size_t)n * 128 + k] = __float2half(W2[(size_t)k * 4096 + n]);
        return;
    }
    __shared__ float row[19];
    __shared__ float eah[12];
    int e = blockIdx.x;
    if (tid < 19) row[tid] = ea_in[(size_t)e * 19 + tid];
    __syncthreads();
    if (tid < 12) {
        float a = b_ea[tid];
#pragma unroll
        for (int i = 0; i < 19; i++) a += row[i] * W_ea[i * 12 + tid];
        eah[tid] = fmaxf(a, 0.f);
    }
    __syncthreads();
    float a = b_e1[tid];
#pragma unroll
    for (int k = 0; k < 12; k++) a += eah[k] * W_e1[k * 128 + tid];
    g_hr_h[(size_t)e * 128 + tid] = __float2half(fmaxf(a, 0.f));
}

// ============ HMMA Wedge GEMM (R6-exact: fp32 acc, 8 warps, 32x64 tiles) ======
#define WSTRIDE 136
#define AS_OFF  0
#define BS_OFF  (128 * WSTRIDE * 2)
#define BIAS_OFF (2 * 128 * WSTRIDE * 2)
#define WM_SMEM_SIZE (BIAS_OFF + 128 * 4)
#define CBSTR 144   // byte stride of fp8 staging rows (16-aligned)

__global__ void __launch_bounds__(256) wedge_mma_kernel(
    const float* __restrict__ b2, int E) {
    extern __shared__ char smem[];
    __half* As = (__half*)(smem + AS_OFF);
    __half* Bs = (__half*)(smem + BS_OFF);
    float* sbias = (float*)(smem + BIAS_OFF);
    uint32_t sbase = smem_to_u32(smem);
    int tid = threadIdx.x;
    int ebase = blockIdx.x * 128;
    int colbase = blockIdx.y * 128;

    if (tid < 128) sbias[tid] = b2[colbase + tid];

#pragma unroll
    for (int it = 0; it < 8; it++) {
        int idx = it * 256 + tid;
        int r = idx >> 4, c = idx & 15;
        uint4 v = make_uint4(0, 0, 0, 0);
        if (ebase + r < E)
            v = *(const uint4*)(g_hr_h + ((size_t)(ebase + r) << 7) + c * 8);
        *(uint4*)(As + r * WSTRIDE + c * 8) = v;
    }
#pragma unroll
    for (int it = 0; it < 8; it++) {
        int idx = it * 256 + tid;
        int r = idx >> 4, c = idx & 15;
        uint4 v = *(const uint4*)(g_W2T + ((size_t)(colbase + r) << 7) + c * 8);
        *(uint4*)(Bs + r * WSTRIDE + c * 8) = v;
    }
    __syncthreads();

    int w = tid >> 5, lane = tid & 31;
    int wm = (w & 3) * 32;
    int wn = (w >> 2) * 64;

    float acc[2][8][4];
#pragma unroll
    for (int i = 0; i < 2; i++)
#pragma unroll
        for (int j = 0; j < 8; j++)
#pragma unroll
            for (int q = 0; q < 4; q++) acc[i][j][q] = 0.f;

    uint32_t a_addr[2];
#pragma unroll
    for (int i = 0; i < 2; i++)
        a_addr[i] = sbase + AS_OFF +
                    (uint32_t)((wm + i * 16 + (lane & 15)) * WSTRIDE +
                               (lane >> 4) * 8) * 2;
    uint32_t b_addr[4];
#pragma unroll
    for (int jj = 0; jj < 4; jj++)
        b_addr[jj] = sbase + BS_OFF +
                     (uint32_t)((wn + jj * 16 + ((lane >> 4) & 1) * 8 + (lane & 7)) *
                                    WSTRIDE +
                                ((lane >> 3) & 1) * 8) * 2;

#pragma unroll
    for (int s = 0; s < 8; s++) {
        uint32_t a[2][4], b[4][4];
#pragma unroll
        for (int i = 0; i < 2; i++) ldsm4(a[i], a_addr[i] + s * 32);
#pragma unroll
        for (int jj = 0; jj < 4; jj++) ldsm4(b[jj], b_addr[jj] + s * 32);
#pragma unroll
        for (int i = 0; i < 2; i++)
#pragma unroll
            for (int jj = 0; jj < 4; jj++) {
                mma16816(acc[i][2 * jj], a[i], &b[jj][0]);
                mma16816(acc[i][2 * jj + 1], a[i], &b[jj][2]);
            }
    }
    __syncthreads();   // reuse smem as fp8 staging

    uint8_t* Cs = (uint8_t*)smem;
    int g = lane >> 2, tg = lane & 3;
#pragma unroll
    for (int i = 0; i < 2; i++) {
#pragma unroll
        for (int j = 0; j < 8; j++) {
            int col = wn + j * 8 + tg * 2;
            float b0 = sbias[col], b1 = sbias[col + 1];
            int r0 = wm + i * 16 + g;
            uint16_t p0 = f32x2_to_e4m3((acc[i][j][0] + b0) * WSCALE,
                                        (acc[i][j][1] + b1) * WSCALE);
            uint16_t p1 = f32x2_to_e4m3((acc[i][j][2] + b0) * WSCALE,
                                        (acc[i][j][3] + b1) * WSCALE);
            *(uint16_t*)(Cs + r0 * CBSTR + col) = p0;
            *(uint16_t*)(Cs + (r0 + 8) * CBSTR + col) = p1;
        }
    }
    __syncthreads();

#pragma unroll
    for (int it = 0; it < 4; it++) {
        int idx = it * 256 + tid;
        int r = idx >> 3, c = idx & 7;
        if (ebase + r < E) {
            uint4 v = *(const uint4*)(Cs + r * CBSTR + c * 16);
            *(uint4*)(g_Wedge8 + (size_t)(ebase + r) * 4096 + colbase + c * 16) = v;
        }
    }
}

// ============ HMMA GRU gate GEMM ==============================================
// gates[N,256] = mh[N,128] @ WcatT[256,128]^T. Same structure as wedge GEMM.
// grid: ((N+127)/128, 2); fp32 output, no bias.
#define GM_SMEM_SIZE (2 * 128 * WSTRIDE * 2)
#define CFSTR 132   // float stride of fp32 staging rows

__global__ void __launch_bounds__(256) gru_mma_kernel(int N) {
    extern __shared__ char smem[];
    __half* As = (__half*)(smem + AS_OFF);
    __half* Bs = (__half*)(smem + BS_OFF);
    uint32_t sbase = smem_to_u32(smem);
    int tid = threadIdx.x;
    int nb = blockIdx.x * 128;
    int colbase = blockIdx.y * 128;

#pragma unroll
    for (int it = 0; it < 8; it++) {
        int idx = it * 256 + tid;
        int r = idx >> 4, c = idx & 15;
        uint4 v = make_uint4(0, 0, 0, 0);
        if (nb + r < N)
            v = *(const uint4*)(g_mh + ((size_t)(nb + r) << 7) + c * 8);
        *(uint4*)(As + r * WSTRIDE + c * 8) = v;
    }
#pragma unroll
    for (int it = 0; it < 8; it++) {
        int idx = it * 256 + tid;
        int r = idx >> 4, c = idx & 15;
        uint4 v = *(const uint4*)(g_WcatT + ((size_t)(colbase + r) << 7) + c * 8);
        *(uint4*)(Bs + r * WSTRIDE + c * 8) = v;
    }
    __syncthreads();

    int w = tid >> 5, lane = tid & 31;
    int wm = (w & 3) * 32;
    int wn = (w >> 2) * 64;

    float acc[2][8][4];
#pragma unroll
    for (int i = 0; i < 2; i++)
#pragma unroll
        for (int j = 0; j < 8; j++)
#pragma unroll
            for (int q = 0; q < 4; q++) acc[i][j][q] = 0.f;

    uint32_t a_addr[2];
#pragma unroll
    for (int i = 0; i < 2; i++)
        a_addr[i] = sbase + AS_OFF +
                    (uint32_t)((wm + i * 16 + (lane & 15)) * WSTRIDE +
                               (lane >> 4) * 8) * 2;
    uint32_t b_addr[4];
#pragma unroll
    for (int jj = 0; jj < 4; jj++)
        b_addr[jj] = sbase + BS_OFF +
                     (uint32_t)((wn + jj * 16 + ((lane >> 4) & 1) * 8 + (lane & 7)) *
                                    WSTRIDE +
                                ((lane >> 3) & 1) * 8) * 2;

#pragma unroll
    for (int s = 0; s < 8; s++) {
        uint32_t a[2][4], b[4][4];
#pragma unroll
        for (int i = 0; i < 2; i++) ldsm4(a[i], a_addr[i] + s * 32);
#pragma unroll
        for (int jj = 0; jj < 4; jj++) ldsm4(b[jj], b_addr[jj] + s * 32);
#pragma unroll
        for (int i = 0; i < 2; i++)
#pragma unroll
            for (int jj = 0; jj < 4; jj++) {
                mma16816(acc[i][2 * jj], a[i], &b[jj][0]);
                mma16816(acc[i][2 * jj + 1], a[i], &b[jj][2]);
            }
    }
    __syncthreads();   // reuse smem as fp32 staging

    float* Cs = (float*)smem;
    int g = lane >> 2, tg = lane & 3;
#pragma unroll
    for (int i = 0; i < 2; i++) {
#pragma unroll
        for (int j = 0; j < 8; j++) {
            int col = wn + j * 8 + tg * 2;
            int r0 = wm + i * 16 + g;
            *(float2*)&Cs[r0 * CFSTR + col] = make_float2(acc[i][j][0], acc[i][j][1]);
            *(float2*)&Cs[(r0 + 8) * CFSTR + col] = make_float2(acc[i][j][2], acc[i][j][3]);
        }
    }
    __syncthreads();

#pragma unroll
    for (int it = 0; it < 16; it++) {
        int idx = it * 256 + tid;
        int r = idx >> 5, c = idx & 31;
        if (nb + r < N) {
            float4 v = *(const float4*)&Cs[r * CFSTR + c * 4];
            *(float4*)&g_gates[(size_t)(nb + r) * 256 + colbase + c * 4] = v;
        }
    }
}

// pack [m|h] into fp16 for the gate GEMM; clears g_agg for next iteration.
__global__ void mh16_kernel(const float* __restrict__ conv_bias, int N) {
    int i = blockIdx.x * 256 + threadIdx.x;
    if (i >= N * DIM) return;
    int n = i >> 6, f = i & 63;
    float m = fmaxf(g_agg[i] * g_invcnt[n] + conv_bias[f], 0.f);
    g_agg[i] = 0.f;
    g_mh[(size_t)n * 128 + f] = __float2half(m);
    g_mh[(size_t)n * 128 + 64 + f] = __float2half(g_h[i]);
}

// elementwise GRU update from gates: r,z combined (ih+hh); inn/hn separate.
__global__ void gru_elem_kernel(const float* __restrict__ b_ih,
                                const float* __restrict__ b_hh, int N) {
    int i = blockIdx.x * 256 + threadIdx.x;
    if (i >= N * DIM) return;
    int n = i >> 6, f = i & 63;
    const float* gt = g_gates + (size_t)n * 256;
    float r = 1.f / (1.f + __expf(-(gt[f] + b_ih[f] + b_hh[f])));
    float z = 1.f / (1.f + __expf(-(gt[64 + f] + b_ih[64 + f] + b_hh[64 + f])));
    float inn = gt[128 + f] + b_ih[128 + f];
    float hn  = gt[192 + f] + b_hh[128 + f];
    float ng = tanhf(inn + r * hn);
    g_h[i] = (1.f - z) * ng + z * g_h[i];
}

// msg[e] = h[src[e]] @ Wedge8[e]; HFMA2 accumulation, scatter via atomics.
__global__ void __launch_bounds__(256) msg_scatter_kernel(
    const int* __restrict__ src, const int* __restrict__ dst, int E) {
    __shared__ uint32_t souts[64][68];
    __shared__ int sdst[64];
    int ty = threadIdx.x >> 2;
    int tx = threadIdx.x & 3;
    int e = blockIdx.x * 64 + ty;
    if (e < E) {
        int s = src[e];
#pragma unroll
        for (int q = 0; q < 4; q++) {
            float4 v = *(const float4*)&g_h[(size_t)s * 64 + tx * 16 + q * 4];
            __half hx = __float2half(v.x), hy = __float2half(v.y);
            __half hz = __float2half(v.z), hw = __float2half(v.w);
            __half2 d0 = __halves2half2(hx, hx);
            __half2 d1 = __halves2half2(hy, hy);
            __half2 d2 = __halves2half2(hz, hz);
            __half2 d3 = __halves2half2(hw, hw);
            souts[ty][tx * 16 + q * 4 + 0] = *(uint32_t*)&d0;
            souts[ty][tx * 16 + q * 4 + 1] = *(uint32_t*)&d1;
            souts[ty][tx * 16 + q * 4 + 2] = *(uint32_t*)&d2;
            souts[ty][tx * 16 + q * 4 + 3] = *(uint32_t*)&d3;
        }
        if (tx == 0) sdst[ty] = dst[e];
    }
    __syncthreads();
    if (e >= E) return;
    __half2 hacc[8];
#pragma unroll
    for (int j = 0; j < 8; j++) hacc[j] = __halves2half2(__ushort_as_half(0),
                                                         __ushort_as_half(0));
    const uint8_t* Wrow = g_Wedge8 + (size_t)e * 4096 + tx * 16;
#pragma unroll 8
    for (int d = 0; d < 64; d++) {
        uint32_t a2 = souts[ty][d];
        __half2 ah = *(__half2*)&a2;
        uint4 raw = *(const uint4*)(Wrow + d * 64);
        uint32_t ws[4] = {raw.x, raw.y, raw.z, raw.w};
#pragma unroll
        for (int q = 0; q < 4; q++) {
            uint32_t lo = e4m3x2_to_f16x2((uint16_t)ws[q]);
            uint32_t hi = e4m3x2_to_f16x2((uint16_t)(ws[q] >> 16));
            hacc[2 * q]     = __hfma2(ah, *(__half2*)&lo, hacc[2 * q]);
            hacc[2 * q + 1] = __hfma2(ah, *(__half2*)&hi, hacc[2 * q + 1]);
        }
    }
    int dn = sdst[ty];
    float* ap = g_agg + (size_t)dn * 64 + tx * 16;
#pragma unroll
    for (int j = 0; j < 8; j++) {
        float2 f = __half22float2(hacc[j]);
        atomicAdd(ap + 2 * j, f.x * WSCALE_INV);
        atomicAdd(ap + 2 * j + 1, f.y * WSCALE_INV);
    }
}

// final MLP: warp-per-edge, weights staged once, no block syncs in edge loop.
#define FIN_EDGES 64
__global__ void __launch_bounds__(128) final_mlp_kernel(
    const float* __restrict__ ea3, const int* __restrict__ idx_a,
    const int* __restrict__ idx_b, const float* __restrict__ W_l1,
    const float* __restrict__ b_l1, const float* __restrict__ W_l2,
    const float* __restrict__ b_l2, float* __restrict__ out, int E3) {
    __shared__ float wl1[72 * 128];
    __shared__ float swl2[128];
    __shared__ float sbl1[128];
    __shared__ float feat[4][72];
    int tid = threadIdx.x;
    for (int i = tid; i < 72 * 128; i += 128) wl1[i] = W_l1[i];
    swl2[tid] = W_l2[tid];
    sbl1[tid] = b_l1[tid];
    __syncthreads();
    int w = tid >> 5, lane = tid & 31;
    float bl2v = b_l2[0];
    int base = blockIdx.x * FIN_EDGES;
    for (int t = w; t < FIN_EDGES; t += 4) {
        int e = base + t;
        if (e >= E3) break;
        int a = idx_a[e], b = idx_b[e];
        feat[w][lane] =
            0.5f * (g_h[(size_t)a * 64 + lane] + g_h[(size_t)b * 64 + lane]);
        feat[w][32 + lane] = 0.5f * (g_h[(size_t)a * 64 + 32 + lane] +
                                     g_h[(size_t)b * 64 + 32 + lane]);
        if (lane < 8) feat[w][64 + lane] = ea3[(size_t)e * 8 + lane];
        __syncwarp();
        float a0 = sbl1[lane], a1 = sbl1[lane + 32],
              a2 = sbl1[lane + 64], a3 = sbl1[lane + 96];
#pragma unroll 8
        for (int i = 0; i < 72; i++) {
            float f = feat[w][i];
            a0 += f * wl1[i * 128 + lane];
            a1 += f * wl1[i * 128 + lane + 32];
            a2 += f * wl1[i * 128 + lane + 64];
            a3 += f * wl1[i * 128 + lane + 96];
        }
        float s = fmaxf(a0, 0.f) * swl2[lane] + fmaxf(a1, 0.f) * swl2[lane + 32] +
                  fmaxf(a2, 0.f) * swl2[lane + 64] + fmaxf(a3, 0.f) * swl2[lane + 96];
#pragma unroll
        for (int o = 16; o > 0; o >>= 1) s += __shfl_down_sync(0xffffffffu, s, o);
        if (lane == 0) out[e] = s + bl2v;
        __syncwarp();
    }
}

// ---------------- launch ------------------------------------------------------
extern "C" void kernel_launch(void* const* d_in, const int* in_sizes, int n_in,
                              void* d_out, int out_size) {
    const float* x          = (const float*)d_in[0];
    const float* edge_attr  = (const float*)d_in[1];
    const float* edge_attr3 = (const float*)d_in[2];
    const int*   edge_index  = (const int*)d_in[3];
    const int*   edge_index3 = (const int*)d_in[4];
    const float* W_node = (const float*)d_in[5];
    const float* b_node = (const float*)d_in[6];
    const float* W_ea   = (const float*)d_in[7];
    const float* b_ea   = (const float*)d_in[8];
    const float* W_e1   = (const float*)d_in[9];
    const float* b_e1   = (const float*)d_in[10];
    const float* W_e2   = (const float*)d_in[11];
    const float* b_e2   = (const float*)d_in[12];
    const float* conv_bias = (const float*)d_in[13];
    const float* W_ih = (const float*)d_in[14];
    const float* b_ih = (const float*)d_in[15];
    const float* W_hh = (const float*)d_in[16];
    const float* b_hh = (const float*)d_in[17];
    const float* W_l1 = (const float*)d_in[18];
    const float* b_l1 = (const float*)d_in[19];
    const float* W_l2 = (const float*)d_in[20];
    const float* b_l2 = (const float*)d_in[21];

    int N  = in_sizes[0] / 8;
    int E  = in_sizes[1] / 19;
    int E3 = in_sizes[2] / 8;
    const int* src  = edge_index;
    const int* dst  = edge_index + E;
    const int* e3a  = edge_index3;
    const int* e3b  = edge_index3 + E3;
    float* out = (float*)d_out;

    cudaFuncSetAttribute(wedge_mma_kernel,
                         cudaFuncAttributeMaxDynamicSharedMemorySize, WM_SMEM_SIZE);
    cudaFuncSetAttribute(gru_mma_kernel,
                         cudaFuncAttributeMaxDynamicSharedMemorySize, GM_SMEM_SIZE);

    // (1) node MLP + zero agg/cnt
    prep_kernel<<<(N * DIM + 255) / 256, 256>>>(x, W_node, b_node, N);
    // (2) edge MLP + W_e2 transpose (fused)
    edge_w2t_kernel<<<E + 4096, 128>>>(edge_attr, W_ea, b_ea, W_e1, b_e1, W_e2, E);
    // (3) GRU gate-weight concat (tiny)
    wcat_kernel<<<128, 256>>>(W_ih, W_hh);
    // (4) big GEMM on tensor cores -> Wedge (e4m3*32)
    {
        dim3 grid((E + 127) / 128, 32);
        wedge_mma_kernel<<<grid, 256, WM_SMEM_SIZE>>>(b_e2, E);
    }
    // (5,6) degree counts
    count_kernel<<<(E + 255) / 256, 256>>>(dst, E);
    invcnt_kernel<<<(N + 255) / 256, 256>>>(N);
    // 3 conv + GRU iterations
    dim3 ggrid((N + 127) / 128, 2);
    for (int it = 0; it < 3; it++) {
        msg_scatter_kernel<<<(E + 63) / 64, 256>>>(src, dst, E);
        mh16_kernel<<<(N * DIM + 255) / 256, 256>>>(conv_bias, N);
        gru_mma_kernel<<<ggrid, 256, GM_SMEM_SIZE>>>(N);
        gru_elem_kernel<<<(N * DIM + 255) / 256, 256>>>(b_ih, b_hh, N);
    }
    // final pair MLP
    final_mlp_kernel<<<(E3 + FIN_EDGES - 1) / FIN_EDGES, 128>>>(
        edge_attr3, e3a, e3b, W_l1, b_l1, W_l2, b_l2, out, E3);
}